// round 15
// baseline (speedup 1.0000x reference)
#include <cuda_runtime.h>
#include <cuda_fp16.h>
#include <math.h>
#include <stdint.h>

// ============================================================================
// QueST: 2-layer LSTM cell + 2-layer MLP head, fp32 semantics.
// Engine: mma.sync.m16n8k16 fp16, f32 accumulate, pure fp16 operands.
// R15: CUTLASS shape — CTA 128x128, 4 warps (warp tile 64x64), 128 threads,
// register fragment double-buffering across k-steps, 3-stage single-barrier
// cp.async pipeline, 2 CTAs/SM.
// ============================================================================

#define SWZ(o)     ((o) ^ (((o) >> 3) & 0x70))
#define STAGE_B    32768                 // A 16K | B 16K
#define NSTAGE     3
#define CSTRIDE    132                   // epilogue f32 stage stride (pad 4)
#define SMEM_BYTES (NSTAGE * STAGE_B)    // 98304; 2 CTAs -> 192KB/SM
#define NTHR       128

// ---- scratch (no cudaMalloc allowed) ---------------------------------------
__device__ __half g_w[20971520];    // fp16 weights: W1 8M | W2 8M | W3 2M | W4 2M
__device__ __half g_A1[8388608];    // [4096,2048] fp16  (X | h1_in)
__device__ __half g_A2[8388608];    // [4096,2048] fp16  (h1 | h2_in)
__device__ __half g_h2[4194304];    // [4096,1024] fp16
__device__ __half g_o3[8388608];    // [4096,2048] fp16

// ---- helpers -----------------------------------------------------------------
__device__ __forceinline__ uint32_t smem_u32(const void* p) {
    uint32_t a;
    asm("{ .reg .u64 t; cvta.to.shared.u64 t, %1; cvt.u32.u64 %0, t; }"
        : "=r"(a) : "l"(p));
    return a;
}
__device__ __forceinline__ void cp16(uint32_t dst, const void* src) {
    asm volatile("cp.async.cg.shared.global [%0], [%1], 16;" :: "r"(dst), "l"(src));
}
__device__ __forceinline__ void cp_commit() {
    asm volatile("cp.async.commit_group;" ::: "memory");
}
__device__ __forceinline__ void cp_wait1() {
    asm volatile("cp.async.wait_group 1;" ::: "memory");
}
__device__ __forceinline__ void ldsm4(uint32_t& r0, uint32_t& r1, uint32_t& r2,
                                      uint32_t& r3, uint32_t a) {
    asm volatile("ldmatrix.sync.aligned.m8n8.x4.shared.b16 {%0,%1,%2,%3}, [%4];"
                 : "=r"(r0), "=r"(r1), "=r"(r2), "=r"(r3) : "r"(a));
}
__device__ __forceinline__ void mmaF32(float* d, const uint32_t* a,
                                       uint32_t b0, uint32_t b1) {
    asm volatile(
        "mma.sync.aligned.m16n8k16.row.col.f32.f16.f16.f32 "
        "{%0,%1,%2,%3}, {%4,%5,%6,%7}, {%8,%9}, {%0,%1,%2,%3};"
        : "+f"(d[0]), "+f"(d[1]), "+f"(d[2]), "+f"(d[3])
        : "r"(a[0]), "r"(a[1]), "r"(a[2]), "r"(a[3]), "r"(b0), "r"(b1));
}
__device__ __forceinline__ float sigm(float x) { return 1.0f / (1.0f + expf(-x)); }

// ---- GEMM mainloop: C[128,128] += A[128,K] * Wblob[128,K]^T (pure fp16) ------
// 4 warps: wm = wid & 1 (64-row slab), wn = wid >> 1 (64-col slab)
__device__ __forceinline__ void gemm_mainloop(
    const __half* __restrict__ A, const __half* __restrict__ B,
    int K, int m0, int n0b, char* smem, float acc[4][8][4])
{
    const uint32_t sb = smem_u32(smem);
    const int tid  = threadIdx.x;
    const int lane = tid & 31;
    const int wid  = tid >> 5;
    const int wm   = wid & 1;
    const int wn   = wid >> 1;    // 0..1

    const __half* PA = A + (size_t)m0 * K;
    const __half* PB = B + (size_t)n0b * K;

    const int r  = tid >> 3;          // 0..15
    const int c8 = (tid & 7) * 8;     // k element offset (16B chunks)

#define LOAD_STAGE(buf, k0)                                                      \
    {                                                                            \
        uint32_t base = sb + (buf) * STAGE_B;                                    \
        _Pragma("unroll")                                                        \
        for (int it = 0; it < 8; it++) {                                         \
            int rr = r + it * 16;                                                \
            uint32_t so = SWZ(rr * 128 + c8 * 2);                                \
            cp16(base + so,         PA + (size_t)rr * K + (k0) + c8);            \
            cp16(base + 16384 + so, PB + (size_t)rr * K + (k0) + c8);            \
        }                                                                        \
    }

    const int NC = K >> 6;
    LOAD_STAGE(0, 0);  cp_commit();
    LOAD_STAGE(1, 64); cp_commit();

    const uint32_t a_lrow = (lane & 15);
    const uint32_t a_lkb  = (lane >> 4) * 16;
    const uint32_t b_lrow = (lane & 7) + ((lane >> 3) & 1) * 8;

    // fragment double-buffers across k-steps
    uint32_t af[2][4][4], bf[2][4][4];

#define LOAD_FRAGS(slot, bAq, bBq, kb)                                           \
    {                                                                            \
        _Pragma("unroll")                                                        \
        for (int f = 0; f < 4; f++) {                                            \
            uint32_t off = (wm * 64 + f * 16 + a_lrow) * 128 + (kb) + a_lkb;     \
            ldsm4(af[slot][f][0], af[slot][f][1], af[slot][f][2],                \
                  af[slot][f][3], (bAq) + SWZ(off));                             \
        }                                                                        \
        _Pragma("unroll")                                                        \
        for (int nf = 0; nf < 4; nf++) {                                         \
            uint32_t off = (wn * 64 + nf * 16 + b_lrow) * 128 + (kb) + a_lkb;    \
            ldsm4(bf[slot][nf][0], bf[slot][nf][1], bf[slot][nf][2],             \
                  bf[slot][nf][3], (bBq) + SWZ(off));                            \
        }                                                                        \
    }

    int cbuf = 0;
    int lbuf = 2;
    for (int i = 0; i < NC; i++) {
        cp_wait1();
        __syncthreads();

        // issue next chunk's loads FIRST — overlap the whole compute phase
        if (i + 2 < NC) LOAD_STAGE(lbuf, (i + 2) * 64);
        cp_commit();

        const uint32_t bA = sb + cbuf * STAGE_B;
        const uint32_t bB = bA + 16384;

        LOAD_FRAGS(0, bA, bB, 0);
#pragma unroll
        for (int ks = 0; ks < 4; ks++) {
            const int cur = ks & 1;
            if (ks < 3) LOAD_FRAGS(cur ^ 1, bA, bB, (ks + 1) * 32);
            // 32-MMA burst, 32 distinct accumulators
#pragma unroll
            for (int nf = 0; nf < 4; nf++)
#pragma unroll
                for (int f = 0; f < 4; f++) {
                    mmaF32(acc[f][nf * 2 + 0], af[cur][f], bf[cur][nf][0], bf[cur][nf][2]);
                    mmaF32(acc[f][nf * 2 + 1], af[cur][f], bf[cur][nf][1], bf[cur][nf][3]);
                }
        }
        cbuf = (cbuf == NSTAGE - 1) ? 0 : cbuf + 1;
        lbuf = (lbuf == NSTAGE - 1) ? 0 : lbuf + 1;
    }
#undef LOAD_FRAGS
#undef LOAD_STAGE
}

// stage accumulators to SMEM as f32 [128][CSTRIDE]
__device__ __forceinline__ void store_acc(char* smem, float acc[4][8][4]) {
    float* Cs = (float*)smem;
    const int lane = threadIdx.x & 31, wid = threadIdx.x >> 5;
    const int wm = wid & 1, wn = wid >> 1;
#pragma unroll
    for (int f = 0; f < 4; f++)
#pragma unroll
        for (int nf2 = 0; nf2 < 8; nf2++) {
            int m = wm * 64 + f * 16 + (lane >> 2);
            int n = wn * 64 + nf2 * 8 + (lane & 3) * 2;
            Cs[m * CSTRIDE + n]           = acc[f][nf2][0];
            Cs[m * CSTRIDE + n + 1]       = acc[f][nf2][1];
            Cs[(m + 8) * CSTRIDE + n]     = acc[f][nf2][2];
            Cs[(m + 8) * CSTRIDE + n + 1] = acc[f][nf2][3];
        }
}

// ---- LSTM kernel: blob window = [f(32) | i(32) | c(32) | o(32)] per CTA ------
__global__ void __launch_bounds__(NTHR, 2)
lstm_gemm(const __half* __restrict__ A, int K,
          const __half* __restrict__ W,
          const float* __restrict__ bfp, const float* __restrict__ bip,
          const float* __restrict__ bcp, const float* __restrict__ bop,
          const float* __restrict__ c_old,
          float* __restrict__ h_out, float* __restrict__ c_out,
          __half* __restrict__ nxh, int nxK)
{
    extern __shared__ __align__(1024) char smem[];
    float acc[4][8][4];
#pragma unroll
    for (int f = 0; f < 4; f++)
#pragma unroll
        for (int n = 0; n < 8; n++)
#pragma unroll
            for (int j = 0; j < 4; j++) acc[f][n][j] = 0.0f;

    const int m0 = blockIdx.y * 128;
    gemm_mainloop(A, W, K, m0, blockIdx.x * 128, smem, acc);
    __syncthreads();
    store_acc(smem, acc);
    __syncthreads();

    const float* Cs = (const float*)smem;
    const int tid = threadIdx.x;
    const int n0 = blockIdx.x * 32;
#pragma unroll
    for (int it = 0; it < 32; it++) {
        int e = tid + it * NTHR;
        int mr = e >> 5, nc = e & 31;
        int m = m0 + mr, n = n0 + nc;
        float fv = sigm(Cs[mr * CSTRIDE + nc]      + bfp[n]);
        float iv = sigm(Cs[mr * CSTRIDE + 32 + nc] + bip[n]);
        float cd = tanhf(Cs[mr * CSTRIDE + 64 + nc] + bcp[n]);
        float ov = sigm(Cs[mr * CSTRIDE + 96 + nc] + bop[n]);
        float hv = ov * tanhf(cd);                       // double tanh (reference)
        float cv = fv * c_old[(size_t)m * 1024 + n] + cd * iv;
        h_out[(size_t)m * 1024 + n] = hv;
        c_out[(size_t)m * 1024 + n] = cv;
        nxh[(size_t)m * nxK + n] = __float2half(hv);
    }
}

// ---- MLP kernel: mode 1 = relu + fp16 out; mode 0 = fp32 out -----------------
__global__ void __launch_bounds__(NTHR, 2)
mlp_gemm(const __half* __restrict__ A, int K,
         const __half* __restrict__ W,
         const float* __restrict__ bias, int mode,
         float* __restrict__ f32out, __half* __restrict__ oh, int ostride)
{
    extern __shared__ __align__(1024) char smem[];
    float acc[4][8][4];
#pragma unroll
    for (int f = 0; f < 4; f++)
#pragma unroll
        for (int n = 0; n < 8; n++)
#pragma unroll
            for (int j = 0; j < 4; j++) acc[f][n][j] = 0.0f;

    const int m0 = blockIdx.y * 128;
    const int n0 = blockIdx.x * 128;
    gemm_mainloop(A, W, K, m0, n0, smem, acc);
    __syncthreads();
    store_acc(smem, acc);
    __syncthreads();

    const float* Cs = (const float*)smem;
    const int tid = threadIdx.x;
#pragma unroll
    for (int it = 0; it < 128; it++) {
        int e = tid + it * NTHR;
        int mr = e >> 7, nc = e & 127;
        int m = m0 + mr, n = n0 + nc;
        float v = Cs[mr * CSTRIDE + nc] + bias[n];
        if (mode == 1) {
            v = fmaxf(v, 0.0f);
            oh[(size_t)m * ostride + n] = __float2half(v);
        } else {
            f32out[(size_t)m * ostride + n] = v;
        }
    }
}

// ---- merged pre-passes (2 launches total) -------------------------------------
// weights: plain fp16, gate interleave granularity 32:
// blob row = (n/32)*(gates*32) + g*32 + n%32
struct WEnt { const float* src; __half* dst; int K, g, gates; };
struct WPack { WEnt m[10]; };

__global__ void __launch_bounds__(256)
split_wgt_all(WPack P)
{
    const WEnt w = P.m[blockIdx.y];
    int idx = blockIdx.x * 256 + threadIdx.x;        // 0..524287 (x4 elems)
    const int kq = w.K >> 2;
    const int ksh = (w.K == 2048) ? 9 : 8;
    int n = idx >> ksh;
    int c = (idx & (kq - 1)) << 2;
    int outr = (n >> 5) * (w.gates << 5) + (w.g << 5) + (n & 31);
    float4 v = *(const float4*)(w.src + (size_t)n * w.K + c);
    size_t d = (size_t)outr * w.K + c;
    w.dst[d]     = __float2half(v.x);
    w.dst[d + 1] = __float2half(v.y);
    w.dst[d + 2] = __float2half(v.z);
    w.dst[d + 3] = __float2half(v.w);
}

// activations: plain fp16
struct AEnt { const float* src; __half* dst; int off; };
struct APack { AEnt m[3]; };

__global__ void __launch_bounds__(256)
split_act_all(APack P)
{
    const AEnt a = P.m[blockIdx.y];
    int idx = blockIdx.x * 256 + threadIdx.x;        // 0..1048575 (x4 elems)
    int r = idx >> 8;
    int c = (idx & 255) << 2;
    float4 v = *(const float4*)(a.src + (size_t)r * 1024 + c);
    size_t d = (size_t)r * 2048 + a.off + c;
    a.dst[d]     = __float2half(v.x);
    a.dst[d + 1] = __float2half(v.y);
    a.dst[d + 2] = __float2half(v.z);
    a.dst[d + 3] = __float2half(v.w);
}

// ---- launch --------------------------------------------------------------------
extern "C" void kernel_launch(void* const* d_in, const int* in_sizes, int n_in,
                              void* d_out, int out_size) {
    (void)in_sizes; (void)n_in; (void)out_size;
    const float* X    = (const float*)d_in[0];
    const float* h1in = (const float*)d_in[1];
    const float* h2in = (const float*)d_in[2];
    const float* c1in = (const float*)d_in[3];
    const float* c2in = (const float*)d_in[4];
    const float* Wf1 = (const float*)d_in[5];  const float* bf1 = (const float*)d_in[6];
    const float* Wi1 = (const float*)d_in[7];  const float* bi1 = (const float*)d_in[8];
    const float* Wc1 = (const float*)d_in[9];  const float* bc1 = (const float*)d_in[10];
    const float* Wo1 = (const float*)d_in[11]; const float* bo1 = (const float*)d_in[12];
    const float* Wf2 = (const float*)d_in[13]; const float* bf2 = (const float*)d_in[14];
    const float* Wi2 = (const float*)d_in[15]; const float* bi2 = (const float*)d_in[16];
    const float* Wc2 = (const float*)d_in[17]; const float* bc2 = (const float*)d_in[18];
    const float* Wo2 = (const float*)d_in[19]; const float* bo2 = (const float*)d_in[20];
    const float* W3  = (const float*)d_in[21]; const float* b3  = (const float*)d_in[22];
    const float* W4  = (const float*)d_in[23]; const float* b4  = (const float*)d_in[24];

    float* out  = (float*)d_out;
    float* o_h1 = out  + (size_t)4096 * 1024;
    float* o_h2 = o_h1 + (size_t)4096 * 1024;
    float* o_c1 = o_h2 + (size_t)4096 * 1024;
    float* o_c2 = o_c1 + (size_t)4096 * 1024;

    void *pw, *pa1, *pa2, *ph2, *po3;
    cudaGetSymbolAddress(&pw,  g_w);
    cudaGetSymbolAddress(&pa1, g_A1);
    cudaGetSymbolAddress(&pa2, g_A2);
    cudaGetSymbolAddress(&ph2, g_h2);
    cudaGetSymbolAddress(&po3, g_o3);
    __half* W  = (__half*)pw;
    __half* A1 = (__half*)pa1;
    __half* A2 = (__half*)pa2;
    __half* H2 = (__half*)ph2;
    __half* O3 = (__half*)po3;
    __half *W1 = W;              // 8M elems
    __half *W2 = W + 8388608;    // 8M
    __half *W3w = W + 16777216;  // 2M
    __half *W4w = W + 18874368;  // 2M

    cudaFuncSetAttribute(lstm_gemm, cudaFuncAttributeMaxDynamicSharedMemorySize, SMEM_BYTES);
    cudaFuncSetAttribute(mlp_gemm,  cudaFuncAttributeMaxDynamicSharedMemorySize, SMEM_BYTES);

    // launch 0: all weight conversions (gate-interleaved blobs, granularity 32)
    WPack wp = {{
        {Wf1, W1, 2048, 0, 4}, {Wi1, W1, 2048, 1, 4},
        {Wc1, W1, 2048, 2, 4}, {Wo1, W1, 2048, 3, 4},
        {Wf2, W2, 2048, 0, 4}, {Wi2, W2, 2048, 1, 4},
        {Wc2, W2, 2048, 2, 4}, {Wo2, W2, 2048, 3, 4},
        {W3,  W3w, 1024, 0, 1}, {W4,  W4w, 2048, 0, 1},
    }};
    split_wgt_all<<<dim3(2048, 10), 256>>>(wp);

    // launch 1: all activation conversions (plain fp16)
    APack ap = {{
        {X,    A1, 0},
        {h1in, A1, 1024},
        {h2in, A2, 1024},
    }};
    split_act_all<<<dim3(4096, 3), 256>>>(ap);

    // launch 2: LSTM1: z=[X|h1_in], K=2048; writes h1 fp16 into A2 cols 0..1023
    lstm_gemm<<<dim3(32, 32), NTHR, SMEM_BYTES>>>(
        A1, 2048, W1, bf1, bi1, bc1, bo1, c1in, o_h1, o_c1, A2, 2048);
    // launch 3: LSTM2: z=[h1|h2_in], K=2048; writes h2 fp16
    lstm_gemm<<<dim3(32, 32), NTHR, SMEM_BYTES>>>(
        A2, 2048, W2, bf2, bi2, bc2, bo2, c2in, o_h2, o_c2, H2, 1024);
    // launch 4: MLP1: out3 = relu(h2 @ W3^T + b3) -> fp16
    mlp_gemm<<<dim3(16, 32), NTHR, SMEM_BYTES>>>(
        H2, 1024, W3w, b3, 1, nullptr, O3, 2048);
    // launch 5: MLP2: out = out3 @ W4^T + b4 -> fp32   (profiled by -s 5)
    mlp_gemm<<<dim3(8, 32), NTHR, SMEM_BYTES>>>(
        O3, 2048, W4w, b4, 0, out, nullptr, 1024);
}

// round 16
// speedup vs baseline: 1.0257x; 1.0257x over previous
#include <cuda_runtime.h>
#include <cuda_fp16.h>
#include <math.h>
#include <stdint.h>

// ============================================================================
// QueST: 2-layer LSTM cell + 2-layer MLP head, fp32 semantics.
// Engine: mma.sync.m16n8k16 fp16, f32 accumulate, pure fp16 operands.
// R16 = R14 (best: CTA 128x128, 8 warps 32x64, 256 thr, 2 CTAs/SM, 3-stage
// single-barrier cp.async pipeline) + PERSISTENT tile loop (grid = 296) to
// remove wave-quantization tails.
// ============================================================================

#define SWZ(o)     ((o) ^ (((o) >> 3) & 0x70))
#define STAGE_B    32768                 // A 16K | B 16K
#define NSTAGE     3
#define CSTRIDE    132                   // epilogue f32 stage stride (pad 4)
#define SMEM_BYTES (NSTAGE * STAGE_B)    // 98304; 2 CTAs -> 192KB/SM
#define NTHR       256
#define MAXCTA     296                   // 148 SMs x 2 CTAs

// ---- scratch (no cudaMalloc allowed) ---------------------------------------
__device__ __half g_w[20971520];    // fp16 weights: W1 8M | W2 8M | W3 2M | W4 2M
__device__ __half g_A1[8388608];    // [4096,2048] fp16  (X | h1_in)
__device__ __half g_A2[8388608];    // [4096,2048] fp16  (h1 | h2_in)
__device__ __half g_h2[4194304];    // [4096,1024] fp16
__device__ __half g_o3[8388608];    // [4096,2048] fp16

// ---- helpers -----------------------------------------------------------------
__device__ __forceinline__ uint32_t smem_u32(const void* p) {
    uint32_t a;
    asm("{ .reg .u64 t; cvta.to.shared.u64 t, %1; cvt.u32.u64 %0, t; }"
        : "=r"(a) : "l"(p));
    return a;
}
__device__ __forceinline__ void cp16(uint32_t dst, const void* src) {
    asm volatile("cp.async.cg.shared.global [%0], [%1], 16;" :: "r"(dst), "l"(src));
}
__device__ __forceinline__ void cp_commit() {
    asm volatile("cp.async.commit_group;" ::: "memory");
}
__device__ __forceinline__ void cp_wait1() {
    asm volatile("cp.async.wait_group 1;" ::: "memory");
}
__device__ __forceinline__ void ldsm4(uint32_t& r0, uint32_t& r1, uint32_t& r2,
                                      uint32_t& r3, uint32_t a) {
    asm volatile("ldmatrix.sync.aligned.m8n8.x4.shared.b16 {%0,%1,%2,%3}, [%4];"
                 : "=r"(r0), "=r"(r1), "=r"(r2), "=r"(r3) : "r"(a));
}
__device__ __forceinline__ void mmaF32(float* d, const uint32_t* a,
                                       uint32_t b0, uint32_t b1) {
    asm volatile(
        "mma.sync.aligned.m16n8k16.row.col.f32.f16.f16.f32 "
        "{%0,%1,%2,%3}, {%4,%5,%6,%7}, {%8,%9}, {%0,%1,%2,%3};"
        : "+f"(d[0]), "+f"(d[1]), "+f"(d[2]), "+f"(d[3])
        : "r"(a[0]), "r"(a[1]), "r"(a[2]), "r"(a[3]), "r"(b0), "r"(b1));
}
__device__ __forceinline__ float sigm(float x) { return 1.0f / (1.0f + expf(-x)); }

// ---- GEMM mainloop: C[128,128] += A[128,K] * Wblob[128,K]^T (pure fp16) ------
// 8 warps: wm = wid & 3 (32-row slab), wn = wid >> 2 (64-col slab)
__device__ __forceinline__ void gemm_mainloop(
    const __half* __restrict__ A, const __half* __restrict__ B,
    int K, int m0, int n0b, char* smem, float acc[2][8][4])
{
    const uint32_t sb = smem_u32(smem);
    const int tid  = threadIdx.x;
    const int lane = tid & 31;
    const int wid  = tid >> 5;
    const int wm   = wid & 3;
    const int wn   = wid >> 2;    // 0..1

    const __half* PA = A + (size_t)m0 * K;
    const __half* PB = B + (size_t)n0b * K;

    const int r  = tid >> 3;          // 0..31
    const int c8 = (tid & 7) * 8;     // k element offset (16B chunks)

#define LOAD_STAGE(buf, k0)                                                      \
    {                                                                            \
        uint32_t base = sb + (buf) * STAGE_B;                                    \
        _Pragma("unroll")                                                        \
        for (int it = 0; it < 4; it++) {                                         \
            int rr = r + it * 32;                                                \
            uint32_t so = SWZ(rr * 128 + c8 * 2);                                \
            cp16(base + so,         PA + (size_t)rr * K + (k0) + c8);            \
            cp16(base + 16384 + so, PB + (size_t)rr * K + (k0) + c8);            \
        }                                                                        \
    }

    const int NC = K >> 6;
    LOAD_STAGE(0, 0);  cp_commit();
    LOAD_STAGE(1, 64); cp_commit();

    const uint32_t a_lrow = (lane & 15);
    const uint32_t a_lkb  = (lane >> 4) * 16;
    const uint32_t b_lrow = (lane & 7) + ((lane >> 3) & 1) * 8;

    int cbuf = 0;      // compute buffer
    int lbuf = 2;      // load buffer = (i+2) % 3
    for (int i = 0; i < NC; i++) {
        cp_wait1();
        __syncthreads();

        if (i + 2 < NC) LOAD_STAGE(lbuf, (i + 2) * 64);
        cp_commit();

        const uint32_t bA = sb + cbuf * STAGE_B;
        const uint32_t bB = bA + 16384;

#pragma unroll
        for (int ks = 0; ks < 4; ks++) {
            const uint32_t kb = ks * 32;
            uint32_t ah[2][4], bh[4][4];
#pragma unroll
            for (int f = 0; f < 2; f++) {
                uint32_t off = (wm * 32 + f * 16 + a_lrow) * 128 + kb + a_lkb;
                ldsm4(ah[f][0], ah[f][1], ah[f][2], ah[f][3], bA + SWZ(off));
            }
#pragma unroll
            for (int nf = 0; nf < 4; nf++) {
                uint32_t off = (wn * 64 + nf * 16 + b_lrow) * 128 + kb + a_lkb;
                ldsm4(bh[nf][0], bh[nf][1], bh[nf][2], bh[nf][3], bB + SWZ(off));
            }
#pragma unroll
            for (int nf = 0; nf < 4; nf++)
#pragma unroll
                for (int f = 0; f < 2; f++) {
                    mmaF32(acc[f][nf * 2 + 0], ah[f], bh[nf][0], bh[nf][2]);
                    mmaF32(acc[f][nf * 2 + 1], ah[f], bh[nf][1], bh[nf][3]);
                }
        }
        cbuf = (cbuf == NSTAGE - 1) ? 0 : cbuf + 1;
        lbuf = (lbuf == NSTAGE - 1) ? 0 : lbuf + 1;
    }
#undef LOAD_STAGE
}

// stage accumulators to SMEM as f32 [128][CSTRIDE]
__device__ __forceinline__ void store_acc(char* smem, float acc[2][8][4]) {
    float* Cs = (float*)smem;
    const int lane = threadIdx.x & 31, wid = threadIdx.x >> 5;
    const int wm = wid & 3, wn = wid >> 2;
#pragma unroll
    for (int f = 0; f < 2; f++)
#pragma unroll
        for (int nf2 = 0; nf2 < 8; nf2++) {
            int m = wm * 32 + f * 16 + (lane >> 2);
            int n = wn * 64 + nf2 * 8 + (lane & 3) * 2;
            Cs[m * CSTRIDE + n]           = acc[f][nf2][0];
            Cs[m * CSTRIDE + n + 1]       = acc[f][nf2][1];
            Cs[(m + 8) * CSTRIDE + n]     = acc[f][nf2][2];
            Cs[(m + 8) * CSTRIDE + n + 1] = acc[f][nf2][3];
        }
}

// ---- LSTM kernel: persistent over tiles; blob window = [f|i|c|o] x32 ---------
__global__ void __launch_bounds__(NTHR, 2)
lstm_gemm(const __half* __restrict__ A, int K,
          const __half* __restrict__ W,
          const float* __restrict__ bfp, const float* __restrict__ bip,
          const float* __restrict__ bcp, const float* __restrict__ bop,
          const float* __restrict__ c_old,
          float* __restrict__ h_out, float* __restrict__ c_out,
          __half* __restrict__ nxh, int nxK, int ntiles, int gx)
{
    extern __shared__ __align__(1024) char smem[];
    const int tid = threadIdx.x;

    for (int t = blockIdx.x; t < ntiles; t += gridDim.x) {
        const int bx = t % gx;
        const int by = t / gx;
        const int m0 = by * 128;

        float acc[2][8][4];
#pragma unroll
        for (int f = 0; f < 2; f++)
#pragma unroll
            for (int n = 0; n < 8; n++)
#pragma unroll
                for (int j = 0; j < 4; j++) acc[f][n][j] = 0.0f;

        gemm_mainloop(A, W, K, m0, bx * 128, smem, acc);
        __syncthreads();
        store_acc(smem, acc);
        __syncthreads();

        const float* Cs = (const float*)smem;
        const int n0 = bx * 32;
#pragma unroll
        for (int it = 0; it < 16; it++) {
            int e = tid + it * NTHR;
            int mr = e >> 5, nc = e & 31;
            int m = m0 + mr, n = n0 + nc;
            float fv = sigm(Cs[mr * CSTRIDE + nc]      + bfp[n]);
            float iv = sigm(Cs[mr * CSTRIDE + 32 + nc] + bip[n]);
            float cd = tanhf(Cs[mr * CSTRIDE + 64 + nc] + bcp[n]);
            float ov = sigm(Cs[mr * CSTRIDE + 96 + nc] + bop[n]);
            float hv = ov * tanhf(cd);                   // double tanh (reference)
            float cv = fv * c_old[(size_t)m * 1024 + n] + cd * iv;
            h_out[(size_t)m * 1024 + n] = hv;
            c_out[(size_t)m * 1024 + n] = cv;
            nxh[(size_t)m * nxK + n] = __float2half(hv);
        }
        __syncthreads();   // epilogue SMEM aliases stage 0 — fence before next tile
    }
}

// ---- MLP kernel: persistent; mode 1 = relu + fp16 out; mode 0 = fp32 out -----
__global__ void __launch_bounds__(NTHR, 2)
mlp_gemm(const __half* __restrict__ A, int K,
         const __half* __restrict__ W,
         const float* __restrict__ bias, int mode,
         float* __restrict__ f32out, __half* __restrict__ oh, int ostride,
         int ntiles, int gx)
{
    extern __shared__ __align__(1024) char smem[];
    const int tid = threadIdx.x;

    for (int t = blockIdx.x; t < ntiles; t += gridDim.x) {
        const int bx = t % gx;
        const int by = t / gx;
        const int m0 = by * 128;
        const int n0 = bx * 128;

        float acc[2][8][4];
#pragma unroll
        for (int f = 0; f < 2; f++)
#pragma unroll
            for (int n = 0; n < 8; n++)
#pragma unroll
                for (int j = 0; j < 4; j++) acc[f][n][j] = 0.0f;

        gemm_mainloop(A, W, K, m0, n0, smem, acc);
        __syncthreads();
        store_acc(smem, acc);
        __syncthreads();

        const float* Cs = (const float*)smem;
#pragma unroll
        for (int it = 0; it < 64; it++) {
            int e = tid + it * NTHR;
            int mr = e >> 7, nc = e & 127;
            int m = m0 + mr, n = n0 + nc;
            float v = Cs[mr * CSTRIDE + nc] + bias[n];
            if (mode == 1) {
                v = fmaxf(v, 0.0f);
                oh[(size_t)m * ostride + n] = __float2half(v);
            } else {
                f32out[(size_t)m * ostride + n] = v;
            }
        }
        __syncthreads();
    }
}

// ---- merged pre-passes (2 launches total) -------------------------------------
// weights: plain fp16, gate interleave granularity 32:
// blob row = (n/32)*(gates*32) + g*32 + n%32
struct WEnt { const float* src; __half* dst; int K, g, gates; };
struct WPack { WEnt m[10]; };

__global__ void __launch_bounds__(256)
split_wgt_all(WPack P)
{
    const WEnt w = P.m[blockIdx.y];
    int idx = blockIdx.x * 256 + threadIdx.x;        // 0..524287 (x4 elems)
    const int kq = w.K >> 2;
    const int ksh = (w.K == 2048) ? 9 : 8;
    int n = idx >> ksh;
    int c = (idx & (kq - 1)) << 2;
    int outr = (n >> 5) * (w.gates << 5) + (w.g << 5) + (n & 31);
    float4 v = *(const float4*)(w.src + (size_t)n * w.K + c);
    size_t d = (size_t)outr * w.K + c;
    w.dst[d]     = __float2half(v.x);
    w.dst[d + 1] = __float2half(v.y);
    w.dst[d + 2] = __float2half(v.z);
    w.dst[d + 3] = __float2half(v.w);
}

// activations: plain fp16
struct AEnt { const float* src; __half* dst; int off; };
struct APack { AEnt m[3]; };

__global__ void __launch_bounds__(256)
split_act_all(APack P)
{
    const AEnt a = P.m[blockIdx.y];
    int idx = blockIdx.x * 256 + threadIdx.x;        // 0..1048575 (x4 elems)
    int r = idx >> 8;
    int c = (idx & 255) << 2;
    float4 v = *(const float4*)(a.src + (size_t)r * 1024 + c);
    size_t d = (size_t)r * 2048 + a.off + c;
    a.dst[d]     = __float2half(v.x);
    a.dst[d + 1] = __float2half(v.y);
    a.dst[d + 2] = __float2half(v.z);
    a.dst[d + 3] = __float2half(v.w);
}

// ---- launch --------------------------------------------------------------------
extern "C" void kernel_launch(void* const* d_in, const int* in_sizes, int n_in,
                              void* d_out, int out_size) {
    (void)in_sizes; (void)n_in; (void)out_size;
    const float* X    = (const float*)d_in[0];
    const float* h1in = (const float*)d_in[1];
    const float* h2in = (const float*)d_in[2];
    const float* c1in = (const float*)d_in[3];
    const float* c2in = (const float*)d_in[4];
    const float* Wf1 = (const float*)d_in[5];  const float* bf1 = (const float*)d_in[6];
    const float* Wi1 = (const float*)d_in[7];  const float* bi1 = (const float*)d_in[8];
    const float* Wc1 = (const float*)d_in[9];  const float* bc1 = (const float*)d_in[10];
    const float* Wo1 = (const float*)d_in[11]; const float* bo1 = (const float*)d_in[12];
    const float* Wf2 = (const float*)d_in[13]; const float* bf2 = (const float*)d_in[14];
    const float* Wi2 = (const float*)d_in[15]; const float* bi2 = (const float*)d_in[16];
    const float* Wc2 = (const float*)d_in[17]; const float* bc2 = (const float*)d_in[18];
    const float* Wo2 = (const float*)d_in[19]; const float* bo2 = (const float*)d_in[20];
    const float* W3  = (const float*)d_in[21]; const float* b3  = (const float*)d_in[22];
    const float* W4  = (const float*)d_in[23]; const float* b4  = (const float*)d_in[24];

    float* out  = (float*)d_out;
    float* o_h1 = out  + (size_t)4096 * 1024;
    float* o_h2 = o_h1 + (size_t)4096 * 1024;
    float* o_c1 = o_h2 + (size_t)4096 * 1024;
    float* o_c2 = o_c1 + (size_t)4096 * 1024;

    void *pw, *pa1, *pa2, *ph2, *po3;
    cudaGetSymbolAddress(&pw,  g_w);
    cudaGetSymbolAddress(&pa1, g_A1);
    cudaGetSymbolAddress(&pa2, g_A2);
    cudaGetSymbolAddress(&ph2, g_h2);
    cudaGetSymbolAddress(&po3, g_o3);
    __half* W  = (__half*)pw;
    __half* A1 = (__half*)pa1;
    __half* A2 = (__half*)pa2;
    __half* H2 = (__half*)ph2;
    __half* O3 = (__half*)po3;
    __half *W1 = W;              // 8M elems
    __half *W2 = W + 8388608;    // 8M
    __half *W3w = W + 16777216;  // 2M
    __half *W4w = W + 18874368;  // 2M

    cudaFuncSetAttribute(lstm_gemm, cudaFuncAttributeMaxDynamicSharedMemorySize, SMEM_BYTES);
    cudaFuncSetAttribute(mlp_gemm,  cudaFuncAttributeMaxDynamicSharedMemorySize, SMEM_BYTES);

    // launch 0: all weight conversions (gate-interleaved blobs, granularity 32)
    WPack wp = {{
        {Wf1, W1, 2048, 0, 4}, {Wi1, W1, 2048, 1, 4},
        {Wc1, W1, 2048, 2, 4}, {Wo1, W1, 2048, 3, 4},
        {Wf2, W2, 2048, 0, 4}, {Wi2, W2, 2048, 1, 4},
        {Wc2, W2, 2048, 2, 4}, {Wo2, W2, 2048, 3, 4},
        {W3,  W3w, 1024, 0, 1}, {W4,  W4w, 2048, 0, 1},
    }};
    split_wgt_all<<<dim3(2048, 10), 256>>>(wp);

    // launch 1: all activation conversions (plain fp16)
    APack ap = {{
        {X,    A1, 0},
        {h1in, A1, 1024},
        {h2in, A2, 1024},
    }};
    split_act_all<<<dim3(4096, 3), 256>>>(ap);

    // launch 2: LSTM1 (1024 tiles, persistent grid 296)
    lstm_gemm<<<MAXCTA, NTHR, SMEM_BYTES>>>(
        A1, 2048, W1, bf1, bi1, bc1, bo1, c1in, o_h1, o_c1, A2, 2048, 1024, 32);
    // launch 3: LSTM2 (1024 tiles)
    lstm_gemm<<<MAXCTA, NTHR, SMEM_BYTES>>>(
        A2, 2048, W2, bf2, bi2, bc2, bo2, c2in, o_h2, o_c2, H2, 1024, 1024, 32);
    // launch 4: MLP1 (512 tiles)
    mlp_gemm<<<MAXCTA, NTHR, SMEM_BYTES>>>(
        H2, 1024, W3w, b3, 1, nullptr, O3, 2048, 512, 16);
    // launch 5: MLP2 (256 tiles; grid capped at tile count)
    mlp_gemm<<<256, NTHR, SMEM_BYTES>>>(
        O3, 2048, W4w, b4, 0, out, nullptr, 1024, 256, 8);
}

// round 17
// speedup vs baseline: 1.1364x; 1.1079x over previous
#include <cuda_runtime.h>
#include <cuda_fp16.h>
#include <math.h>
#include <stdint.h>

// ============================================================================
// QueST: 2-layer LSTM cell + 2-layer MLP head, fp32 semantics.
// Engine: mma.sync.m16n8k16 fp16, f32 accumulate, pure fp16 operands.
// R17 = R14 champion (CTA 128x128, 8 warps 32x64, 256 thr, 2 CTAs/SM,
// 3-stage single-barrier cp.async pipeline) + m-major grid raster.
// ============================================================================

#define SWZ(o)     ((o) ^ (((o) >> 3) & 0x70))
#define STAGE_B    32768                 // A 16K | B 16K
#define NSTAGE     3
#define CSTRIDE    132                   // epilogue f32 stage stride (pad 4)
#define SMEM_BYTES (NSTAGE * STAGE_B)    // 98304; 2 CTAs -> 192KB/SM
#define NTHR       256

// ---- scratch (no cudaMalloc allowed) ---------------------------------------
__device__ __half g_w[20971520];    // fp16 weights: W1 8M | W2 8M | W3 2M | W4 2M
__device__ __half g_A1[8388608];    // [4096,2048] fp16  (X | h1_in)
__device__ __half g_A2[8388608];    // [4096,2048] fp16  (h1 | h2_in)
__device__ __half g_h2[4194304];    // [4096,1024] fp16
__device__ __half g_o3[8388608];    // [4096,2048] fp16

// ---- helpers -----------------------------------------------------------------
__device__ __forceinline__ uint32_t smem_u32(const void* p) {
    uint32_t a;
    asm("{ .reg .u64 t; cvta.to.shared.u64 t, %1; cvt.u32.u64 %0, t; }"
        : "=r"(a) : "l"(p));
    return a;
}
__device__ __forceinline__ void cp16(uint32_t dst, const void* src) {
    asm volatile("cp.async.cg.shared.global [%0], [%1], 16;" :: "r"(dst), "l"(src));
}
__device__ __forceinline__ void cp_commit() {
    asm volatile("cp.async.commit_group;" ::: "memory");
}
__device__ __forceinline__ void cp_wait1() {
    asm volatile("cp.async.wait_group 1;" ::: "memory");
}
__device__ __forceinline__ void ldsm4(uint32_t& r0, uint32_t& r1, uint32_t& r2,
                                      uint32_t& r3, uint32_t a) {
    asm volatile("ldmatrix.sync.aligned.m8n8.x4.shared.b16 {%0,%1,%2,%3}, [%4];"
                 : "=r"(r0), "=r"(r1), "=r"(r2), "=r"(r3) : "r"(a));
}
__device__ __forceinline__ void mmaF32(float* d, const uint32_t* a,
                                       uint32_t b0, uint32_t b1) {
    asm volatile(
        "mma.sync.aligned.m16n8k16.row.col.f32.f16.f16.f32 "
        "{%0,%1,%2,%3}, {%4,%5,%6,%7}, {%8,%9}, {%0,%1,%2,%3};"
        : "+f"(d[0]), "+f"(d[1]), "+f"(d[2]), "+f"(d[3])
        : "r"(a[0]), "r"(a[1]), "r"(a[2]), "r"(a[3]), "r"(b0), "r"(b1));
}
__device__ __forceinline__ float sigm(float x) { return 1.0f / (1.0f + expf(-x)); }

// ---- GEMM mainloop: C[128,128] += A[128,K] * Wblob[128,K]^T (pure fp16) ------
// 8 warps: wm = wid & 3 (32-row slab), wn = wid >> 2 (64-col slab)
__device__ __forceinline__ void gemm_mainloop(
    const __half* __restrict__ A, const __half* __restrict__ B,
    int K, int m0, int n0b, char* smem, float acc[2][8][4])
{
    const uint32_t sb = smem_u32(smem);
    const int tid  = threadIdx.x;
    const int lane = tid & 31;
    const int wid  = tid >> 5;
    const int wm   = wid & 3;
    const int wn   = wid >> 2;    // 0..1

    const __half* PA = A + (size_t)m0 * K;
    const __half* PB = B + (size_t)n0b * K;

    const int r  = tid >> 3;          // 0..31
    const int c8 = (tid & 7) * 8;     // k element offset (16B chunks)

#define LOAD_STAGE(buf, k0)                                                      \
    {                                                                            \
        uint32_t base = sb + (buf) * STAGE_B;                                    \
        _Pragma("unroll")                                                        \
        for (int it = 0; it < 4; it++) {                                         \
            int rr = r + it * 32;                                                \
            uint32_t so = SWZ(rr * 128 + c8 * 2);                                \
            cp16(base + so,         PA + (size_t)rr * K + (k0) + c8);            \
            cp16(base + 16384 + so, PB + (size_t)rr * K + (k0) + c8);            \
        }                                                                        \
    }

    const int NC = K >> 6;
    // prologue: 2 chunks in flight; 3rd buffer is the write-while-read slack
    LOAD_STAGE(0, 0);  cp_commit();
    LOAD_STAGE(1, 64); cp_commit();

    const uint32_t a_lrow = (lane & 15);
    const uint32_t a_lkb  = (lane >> 4) * 16;
    const uint32_t b_lrow = (lane & 7) + ((lane >> 3) & 1) * 8;

    int cbuf = 0;      // compute buffer
    int lbuf = 2;      // load buffer = (i+2) % 3
    for (int i = 0; i < NC; i++) {
        cp_wait1();            // chunk i resident (i+1 may still be in flight)
        __syncthreads();       // single barrier: also fences buffer (i+2)%3 reuse

        // issue next chunk's loads FIRST — they overlap the whole compute phase
        if (i + 2 < NC) LOAD_STAGE(lbuf, (i + 2) * 64);
        cp_commit();

        const uint32_t bA = sb + cbuf * STAGE_B;
        const uint32_t bB = bA + 16384;

#pragma unroll
        for (int ks = 0; ks < 4; ks++) {
            const uint32_t kb = ks * 32;
            uint32_t ah[2][4], bh[4][4];
#pragma unroll
            for (int f = 0; f < 2; f++) {
                uint32_t off = (wm * 32 + f * 16 + a_lrow) * 128 + kb + a_lkb;
                ldsm4(ah[f][0], ah[f][1], ah[f][2], ah[f][3], bA + SWZ(off));
            }
#pragma unroll
            for (int nf = 0; nf < 4; nf++) {
                uint32_t off = (wn * 64 + nf * 16 + b_lrow) * 128 + kb + a_lkb;
                ldsm4(bh[nf][0], bh[nf][1], bh[nf][2], bh[nf][3], bB + SWZ(off));
            }
#pragma unroll
            for (int nf = 0; nf < 4; nf++)
#pragma unroll
                for (int f = 0; f < 2; f++) {
                    mmaF32(acc[f][nf * 2 + 0], ah[f], bh[nf][0], bh[nf][2]);
                    mmaF32(acc[f][nf * 2 + 1], ah[f], bh[nf][1], bh[nf][3]);
                }
        }
        cbuf = (cbuf == NSTAGE - 1) ? 0 : cbuf + 1;
        lbuf = (lbuf == NSTAGE - 1) ? 0 : lbuf + 1;
    }
#undef LOAD_STAGE
}

// stage accumulators to SMEM as f32 [128][CSTRIDE]
__device__ __forceinline__ void store_acc(char* smem, float acc[2][8][4]) {
    float* Cs = (float*)smem;
    const int lane = threadIdx.x & 31, wid = threadIdx.x >> 5;
    const int wm = wid & 3, wn = wid >> 2;
#pragma unroll
    for (int f = 0; f < 2; f++)
#pragma unroll
        for (int nf2 = 0; nf2 < 8; nf2++) {
            int m = wm * 32 + f * 16 + (lane >> 2);
            int n = wn * 64 + nf2 * 8 + (lane & 3) * 2;
            Cs[m * CSTRIDE + n]           = acc[f][nf2][0];
            Cs[m * CSTRIDE + n + 1]       = acc[f][nf2][1];
            Cs[(m + 8) * CSTRIDE + n]     = acc[f][nf2][2];
            Cs[(m + 8) * CSTRIDE + n + 1] = acc[f][nf2][3];
        }
}

// ---- LSTM kernel: blob window = [f(32) | i(32) | c(32) | o(32)] per CTA ------
// grid: x = m-tile (32), y = n-blob (32)  — m-major raster for weight L2 reuse
__global__ void __launch_bounds__(NTHR, 2)
lstm_gemm(const __half* __restrict__ A, int K,
          const __half* __restrict__ W,
          const float* __restrict__ bfp, const float* __restrict__ bip,
          const float* __restrict__ bcp, const float* __restrict__ bop,
          const float* __restrict__ c_old,
          float* __restrict__ h_out, float* __restrict__ c_out,
          __half* __restrict__ nxh, int nxK)
{
    extern __shared__ __align__(1024) char smem[];
    float acc[2][8][4];
#pragma unroll
    for (int f = 0; f < 2; f++)
#pragma unroll
        for (int n = 0; n < 8; n++)
#pragma unroll
            for (int j = 0; j < 4; j++) acc[f][n][j] = 0.0f;

    const int m0 = blockIdx.x * 128;
    gemm_mainloop(A, W, K, m0, blockIdx.y * 128, smem, acc);
    __syncthreads();
    store_acc(smem, acc);
    __syncthreads();

    const float* Cs = (const float*)smem;
    const int tid = threadIdx.x;
    const int n0 = blockIdx.y * 32;
#pragma unroll
    for (int it = 0; it < 16; it++) {
        int e = tid + it * NTHR;
        int mr = e >> 5, nc = e & 31;
        int m = m0 + mr, n = n0 + nc;
        float fv = sigm(Cs[mr * CSTRIDE + nc]      + bfp[n]);
        float iv = sigm(Cs[mr * CSTRIDE + 32 + nc] + bip[n]);
        float cd = tanhf(Cs[mr * CSTRIDE + 64 + nc] + bcp[n]);
        float ov = sigm(Cs[mr * CSTRIDE + 96 + nc] + bop[n]);
        float hv = ov * tanhf(cd);                       // double tanh (reference)
        float cv = fv * c_old[(size_t)m * 1024 + n] + cd * iv;
        h_out[(size_t)m * 1024 + n] = hv;
        c_out[(size_t)m * 1024 + n] = cv;
        nxh[(size_t)m * nxK + n] = __float2half(hv);
    }
}

// ---- MLP kernel: mode 1 = relu + fp16 out; mode 0 = fp32 out -----------------
// grid: x = m-tile, y = n-tile
__global__ void __launch_bounds__(NTHR, 2)
mlp_gemm(const __half* __restrict__ A, int K,
         const __half* __restrict__ W,
         const float* __restrict__ bias, int mode,
         float* __restrict__ f32out, __half* __restrict__ oh, int ostride)
{
    extern __shared__ __align__(1024) char smem[];
    float acc[2][8][4];
#pragma unroll
    for (int f = 0; f < 2; f++)
#pragma unroll
        for (int n = 0; n < 8; n++)
#pragma unroll
            for (int j = 0; j < 4; j++) acc[f][n][j] = 0.0f;

    const int m0 = blockIdx.x * 128;
    const int n0 = blockIdx.y * 128;
    gemm_mainloop(A, W, K, m0, n0, smem, acc);
    __syncthreads();
    store_acc(smem, acc);
    __syncthreads();

    const float* Cs = (const float*)smem;
    const int tid = threadIdx.x;
#pragma unroll
    for (int it = 0; it < 64; it++) {
        int e = tid + it * NTHR;
        int mr = e >> 7, nc = e & 127;
        int m = m0 + mr, n = n0 + nc;
        float v = Cs[mr * CSTRIDE + nc] + bias[n];
        if (mode == 1) {
            v = fmaxf(v, 0.0f);
            oh[(size_t)m * ostride + n] = __float2half(v);
        } else {
            f32out[(size_t)m * ostride + n] = v;
        }
    }
}

// ---- merged pre-passes (2 launches total) -------------------------------------
// weights: plain fp16, gate interleave granularity 32:
// blob row = (n/32)*(gates*32) + g*32 + n%32
struct WEnt { const float* src; __half* dst; int K, g, gates; };
struct WPack { WEnt m[10]; };

__global__ void __launch_bounds__(256)
split_wgt_all(WPack P)
{
    const WEnt w = P.m[blockIdx.y];
    int idx = blockIdx.x * 256 + threadIdx.x;        // 0..524287 (x4 elems)
    const int kq = w.K >> 2;
    const int ksh = (w.K == 2048) ? 9 : 8;
    int n = idx >> ksh;
    int c = (idx & (kq - 1)) << 2;
    int outr = (n >> 5) * (w.gates << 5) + (w.g << 5) + (n & 31);
    float4 v = *(const float4*)(w.src + (size_t)n * w.K + c);
    size_t d = (size_t)outr * w.K + c;
    w.dst[d]     = __float2half(v.x);
    w.dst[d + 1] = __float2half(v.y);
    w.dst[d + 2] = __float2half(v.z);
    w.dst[d + 3] = __float2half(v.w);
}

// activations: plain fp16
struct AEnt { const float* src; __half* dst; int off; };
struct APack { AEnt m[3]; };

__global__ void __launch_bounds__(256)
split_act_all(APack P)
{
    const AEnt a = P.m[blockIdx.y];
    int idx = blockIdx.x * 256 + threadIdx.x;        // 0..1048575 (x4 elems)
    int r = idx >> 8;
    int c = (idx & 255) << 2;
    float4 v = *(const float4*)(a.src + (size_t)r * 1024 + c);
    size_t d = (size_t)r * 2048 + a.off + c;
    a.dst[d]     = __float2half(v.x);
    a.dst[d + 1] = __float2half(v.y);
    a.dst[d + 2] = __float2half(v.z);
    a.dst[d + 3] = __float2half(v.w);
}

// ---- launch --------------------------------------------------------------------
extern "C" void kernel_launch(void* const* d_in, const int* in_sizes, int n_in,
                              void* d_out, int out_size) {
    (void)in_sizes; (void)n_in; (void)out_size;
    const float* X    = (const float*)d_in[0];
    const float* h1in = (const float*)d_in[1];
    const float* h2in = (const float*)d_in[2];
    const float* c1in = (const float*)d_in[3];
    const float* c2in = (const float*)d_in[4];
    const float* Wf1 = (const float*)d_in[5];  const float* bf1 = (const float*)d_in[6];
    const float* Wi1 = (const float*)d_in[7];  const float* bi1 = (const float*)d_in[8];
    const float* Wc1 = (const float*)d_in[9];  const float* bc1 = (const float*)d_in[10];
    const float* Wo1 = (const float*)d_in[11]; const float* bo1 = (const float*)d_in[12];
    const float* Wf2 = (const float*)d_in[13]; const float* bf2 = (const float*)d_in[14];
    const float* Wi2 = (const float*)d_in[15]; const float* bi2 = (const float*)d_in[16];
    const float* Wc2 = (const float*)d_in[17]; const float* bc2 = (const float*)d_in[18];
    const float* Wo2 = (const float*)d_in[19]; const float* bo2 = (const float*)d_in[20];
    const float* W3  = (const float*)d_in[21]; const float* b3  = (const float*)d_in[22];
    const float* W4  = (const float*)d_in[23]; const float* b4  = (const float*)d_in[24];

    float* out  = (float*)d_out;
    float* o_h1 = out  + (size_t)4096 * 1024;
    float* o_h2 = o_h1 + (size_t)4096 * 1024;
    float* o_c1 = o_h2 + (size_t)4096 * 1024;
    float* o_c2 = o_c1 + (size_t)4096 * 1024;

    void *pw, *pa1, *pa2, *ph2, *po3;
    cudaGetSymbolAddress(&pw,  g_w);
    cudaGetSymbolAddress(&pa1, g_A1);
    cudaGetSymbolAddress(&pa2, g_A2);
    cudaGetSymbolAddress(&ph2, g_h2);
    cudaGetSymbolAddress(&po3, g_o3);
    __half* W  = (__half*)pw;
    __half* A1 = (__half*)pa1;
    __half* A2 = (__half*)pa2;
    __half* H2 = (__half*)ph2;
    __half* O3 = (__half*)po3;
    __half *W1 = W;              // 8M elems
    __half *W2 = W + 8388608;    // 8M
    __half *W3w = W + 16777216;  // 2M
    __half *W4w = W + 18874368;  // 2M

    cudaFuncSetAttribute(lstm_gemm, cudaFuncAttributeMaxDynamicSharedMemorySize, SMEM_BYTES);
    cudaFuncSetAttribute(mlp_gemm,  cudaFuncAttributeMaxDynamicSharedMemorySize, SMEM_BYTES);

    // launch 0: all weight conversions (gate-interleaved blobs, granularity 32)
    WPack wp = {{
        {Wf1, W1, 2048, 0, 4}, {Wi1, W1, 2048, 1, 4},
        {Wc1, W1, 2048, 2, 4}, {Wo1, W1, 2048, 3, 4},
        {Wf2, W2, 2048, 0, 4}, {Wi2, W2, 2048, 1, 4},
        {Wc2, W2, 2048, 2, 4}, {Wo2, W2, 2048, 3, 4},
        {W3,  W3w, 1024, 0, 1}, {W4,  W4w, 2048, 0, 1},
    }};
    split_wgt_all<<<dim3(2048, 10), 256>>>(wp);

    // launch 1: all activation conversions (plain fp16)
    APack ap = {{
        {X,    A1, 0},
        {h1in, A1, 1024},
        {h2in, A2, 1024},
    }};
    split_act_all<<<dim3(4096, 3), 256>>>(ap);

    // launch 2: LSTM1: z=[X|h1_in], K=2048; writes h1 fp16 into A2 cols 0..1023
    lstm_gemm<<<dim3(32, 32), NTHR, SMEM_BYTES>>>(
        A1, 2048, W1, bf1, bi1, bc1, bo1, c1in, o_h1, o_c1, A2, 2048);
    // launch 3: LSTM2: z=[h1|h2_in], K=2048; writes h2 fp16
    lstm_gemm<<<dim3(32, 32), NTHR, SMEM_BYTES>>>(
        A2, 2048, W2, bf2, bi2, bc2, bo2, c2in, o_h2, o_c2, H2, 1024);
    // launch 4: MLP1: out3 = relu(h2 @ W3^T + b3) -> fp16
    mlp_gemm<<<dim3(32, 16), NTHR, SMEM_BYTES>>>(
        H2, 1024, W3w, b3, 1, nullptr, O3, 2048);
    // launch 5: MLP2: out = out3 @ W4^T + b4 -> fp32   (profiled by -s 5)
    mlp_gemm<<<dim3(32, 8), NTHR, SMEM_BYTES>>>(
        O3, 2048, W4w, b4, 0, out, nullptr, 1024);
}